// round 16
// baseline (speedup 1.0000x reference)
#include <cuda_runtime.h>
#include <cuda_bf16.h>
#include <math.h>

#define N_NODES 50000
#define N_EDGES 400000
#define HEADS 8
#define HID 32
#define F 256            // HEADS*HID
#define NEG 0.2f

// ---------------- scratch (device globals: allocation-free) ----------------
__device__ float g_h[N_NODES * F];        // X @ W (pre-attention features)
__device__ float g_x[N_NODES * F];        // layer output
__device__ float g_asrc[N_NODES * HEADS];
__device__ float g_adst[N_NODES * HEADS];
__device__ float g_p[N_NODES * 64];       // [P_a | P_b] node projections
__device__ float g_wcat[256 * 64];        // [Wp1_a | Wp1_b] packed
__device__ int   g_cnt[N_NODES];
__device__ int   g_off[N_NODES + 1];
__device__ int   g_fill[N_NODES];
__device__ int   g_bsum[256];
__device__ int   g_csrc[N_EDGES];

__device__ __forceinline__ float leaky(float x) { return x > 0.f ? x : NEG * x; }

// pack two floats to bf16x2 (x in low half = first k element)
__device__ __forceinline__ unsigned pk(float x, float y) {
    __nv_bfloat162 h = __floats2bfloat162_rn(x, y);
    return *(unsigned*)&h;
}
__device__ __forceinline__ void split2(float x, float y, unsigned& hi, unsigned& lo) {
    float hx = __bfloat162float(__float2bfloat16_rn(x));
    float hy = __bfloat162float(__float2bfloat16_rn(y));
    hi = pk(hx, hy);
    lo = pk(x - hx, y - hy);
}

__device__ __forceinline__ void mma16(float* c,
    unsigned a0, unsigned a1, unsigned a2, unsigned a3,
    unsigned b0, unsigned b1)
{
    asm volatile(
        "mma.sync.aligned.m16n8k16.row.col.f32.bf16.bf16.f32 "
        "{%0,%1,%2,%3}, {%4,%5,%6,%7}, {%8,%9}, {%0,%1,%2,%3};"
        : "+f"(c[0]), "+f"(c[1]), "+f"(c[2]), "+f"(c[3])
        : "r"(a0), "r"(a1), "r"(a2), "r"(a3), "r"(b0), "r"(b1));
}

// ------ layer GEMM: tile 128x128, BK=16, 3x bf16 split, attention epilogue -
// 256 threads = 8 warps (4 warp_m x 2 warp_n), warp tile 32x64 (2 heads).
// Smem double-buffered: ONE __syncthreads per k-tile.
__global__ __launch_bounds__(256) void tc_gemm128_kernel(
    const float* __restrict__ A, const float* __restrict__ B,
    float* __restrict__ C, int M, int K, int ldb, int ldc,
    const float* __restrict__ a_src, const float* __restrict__ a_dst)
{
    __shared__ unsigned Ah[2][8][132], Al[2][8][132];
    __shared__ unsigned Bh[2][8][132], Bl[2][8][132];
    __shared__ float sAs[128], sAd[128];

    const int tid = threadIdx.x;
    const int lane = tid & 31;
    const int wid = tid >> 5;
    const int warp_m = wid >> 1;          // rows warp_m*32
    const int warp_n = wid & 1;           // cols warp_n*64
    const int tig = lane & 3;
    const int grp = lane >> 2;
    const int m0 = blockIdx.x * 128;
    const int n0 = blockIdx.y * 128;

    if (tid < 128) {
        sAs[tid] = a_src[n0 + tid];
        sAd[tid] = a_dst[n0 + tid];
    }

    const int am0 = tid >> 2;             // 0..63
    const int am1 = am0 + 64;             // 64..127
    const int akp = (tid & 3) * 2;
    const int bn = tid & 127;
    const int bkh = tid >> 7;             // 0 or 1

    float acc[2][8][4];
#pragma unroll
    for (int mf = 0; mf < 2; ++mf)
#pragma unroll
        for (int nf = 0; nf < 8; ++nf)
#pragma unroll
            for (int j = 0; j < 4; ++j) acc[mf][nf][j] = 0.f;

    // ---- prologue: prefetch tile 0 ----
    float4 va0 = make_float4(0.f, 0.f, 0.f, 0.f);
    float4 va1 = make_float4(0.f, 0.f, 0.f, 0.f);
    float pb[8];
    if (m0 + am0 < M) va0 = *(const float4*)&A[(size_t)(m0 + am0) * K + akp * 2];
    if (m0 + am1 < M) va1 = *(const float4*)&A[(size_t)(m0 + am1) * K + akp * 2];
#pragma unroll
    for (int q = 0; q < 4; ++q) {
        int kp = bkh + 2 * q;
        pb[2 * q]     = B[(size_t)(2 * kp) * ldb + n0 + bn];
        pb[2 * q + 1] = B[(size_t)(2 * kp + 1) * ldb + n0 + bn];
    }

    int buf = 0;
    for (int k0 = 0; k0 < K; k0 += 16) {
        {
            unsigned h, l;
            split2(va0.x, va0.y, h, l); Ah[buf][akp][am0] = h;     Al[buf][akp][am0] = l;
            split2(va0.z, va0.w, h, l); Ah[buf][akp + 1][am0] = h; Al[buf][akp + 1][am0] = l;
            split2(va1.x, va1.y, h, l); Ah[buf][akp][am1] = h;     Al[buf][akp][am1] = l;
            split2(va1.z, va1.w, h, l); Ah[buf][akp + 1][am1] = h; Al[buf][akp + 1][am1] = l;
#pragma unroll
            for (int q = 0; q < 4; ++q) {
                int kp = bkh + 2 * q;
                split2(pb[2 * q], pb[2 * q + 1], h, l);
                Bh[buf][kp][bn] = h; Bl[buf][kp][bn] = l;
            }
        }
        __syncthreads();

        if (k0 + 16 < K) {
            va0 = make_float4(0.f, 0.f, 0.f, 0.f);
            va1 = make_float4(0.f, 0.f, 0.f, 0.f);
            if (m0 + am0 < M) va0 = *(const float4*)&A[(size_t)(m0 + am0) * K + k0 + 16 + akp * 2];
            if (m0 + am1 < M) va1 = *(const float4*)&A[(size_t)(m0 + am1) * K + k0 + 16 + akp * 2];
#pragma unroll
            for (int q = 0; q < 4; ++q) {
                int kp = bkh + 2 * q;
                pb[2 * q]     = B[(size_t)(k0 + 16 + 2 * kp) * ldb + n0 + bn];
                pb[2 * q + 1] = B[(size_t)(k0 + 16 + 2 * kp + 1) * ldb + n0 + bn];
            }
        }

        unsigned ah[2][4], al_[2][4];
#pragma unroll
        for (int mf = 0; mf < 2; ++mf) {
            int mb = warp_m * 32 + mf * 16 + grp;
            ah[mf][0] = Ah[buf][tig][mb];      al_[mf][0] = Al[buf][tig][mb];
            ah[mf][1] = Ah[buf][tig][mb + 8];  al_[mf][1] = Al[buf][tig][mb + 8];
            ah[mf][2] = Ah[buf][tig + 4][mb];      al_[mf][2] = Al[buf][tig + 4][mb];
            ah[mf][3] = Ah[buf][tig + 4][mb + 8];  al_[mf][3] = Al[buf][tig + 4][mb + 8];
        }
#pragma unroll
        for (int nf = 0; nf < 8; ++nf) {
            int n = warp_n * 64 + nf * 8 + grp;
            unsigned bh0 = Bh[buf][tig][n], bh1 = Bh[buf][tig + 4][n];
            unsigned bl0 = Bl[buf][tig][n], bl1 = Bl[buf][tig + 4][n];
#pragma unroll
            for (int mf = 0; mf < 2; ++mf) {
                mma16(acc[mf][nf], ah[mf][0], ah[mf][1], ah[mf][2], ah[mf][3], bh0, bh1);
                mma16(acc[mf][nf], al_[mf][0], al_[mf][1], al_[mf][2], al_[mf][3], bh0, bh1);
                mma16(acc[mf][nf], ah[mf][0], ah[mf][1], ah[mf][2], ah[mf][3], bl0, bl1);
            }
        }
        buf ^= 1;        // next store targets the other buffer — no trailing sync
    }

    // ---- store C ----
#pragma unroll
    for (int mf = 0; mf < 2; ++mf) {
        int r0 = m0 + warp_m * 32 + mf * 16 + grp;
        int r1 = r0 + 8;
#pragma unroll
        for (int nf = 0; nf < 8; ++nf) {
            int c = n0 + warp_n * 64 + nf * 8 + tig * 2;
            if (r0 < M)
                *(float2*)&C[(size_t)r0 * ldc + c] = make_float2(acc[mf][nf][0], acc[mf][nf][1]);
            if (r1 < M)
                *(float2*)&C[(size_t)r1 * ldc + c] = make_float2(acc[mf][nf][2], acc[mf][nf][3]);
        }
    }

    // ---- attention dots: warp spans 2 heads (nf 0..3 and nf 4..7) ----
#pragma unroll
    for (int mf = 0; mf < 2; ++mf) {
#pragma unroll
        for (int half = 0; half < 2; ++half) {
            const int head = (n0 >> 5) + warp_n * 2 + half;
            float ps0 = 0.f, pd0 = 0.f, ps1 = 0.f, pd1 = 0.f;
#pragma unroll
            for (int q = 0; q < 4; ++q) {
                int nf = half * 4 + q;
                int cl = warp_n * 64 + nf * 8 + tig * 2;
                float w0s = sAs[cl], w1s = sAs[cl + 1];
                float w0d = sAd[cl], w1d = sAd[cl + 1];
                ps0 += acc[mf][nf][0] * w0s + acc[mf][nf][1] * w1s;
                pd0 += acc[mf][nf][0] * w0d + acc[mf][nf][1] * w1d;
                ps1 += acc[mf][nf][2] * w0s + acc[mf][nf][3] * w1s;
                pd1 += acc[mf][nf][2] * w0d + acc[mf][nf][3] * w1d;
            }
#pragma unroll
            for (int off = 1; off <= 2; off <<= 1) {
                ps0 += __shfl_xor_sync(0xffffffffu, ps0, off);
                pd0 += __shfl_xor_sync(0xffffffffu, pd0, off);
                ps1 += __shfl_xor_sync(0xffffffffu, ps1, off);
                pd1 += __shfl_xor_sync(0xffffffffu, pd1, off);
            }
            if (tig == 0) {
                int r0 = m0 + warp_m * 32 + mf * 16 + grp;
                int r1 = r0 + 8;
                if (r0 < M) { g_asrc[r0 * 8 + head] = ps0; g_adst[r0 * 8 + head] = pd0; }
                if (r1 < M) { g_asrc[r1 * 8 + head] = ps1; g_adst[r1 * 8 + head] = pd1; }
            }
        }
    }
}

// ------ proj GEMM: tile 128x64, BK=16 (round-12 verified kernel) -----------
__global__ __launch_bounds__(256) void tc_gemm_kernel(
    const float* __restrict__ A, const float* __restrict__ B,
    float* __restrict__ C, int M, int K, int ldb, int ldc)
{
    __shared__ unsigned Ah[8][132], Al[8][132];
    __shared__ unsigned Bh[8][68],  Bl[8][68];

    const int tid = threadIdx.x;
    const int lane = tid & 31;
    const int wid = tid >> 5;
    const int warp_m = wid >> 1;
    const int warp_n = wid & 1;
    const int tig = lane & 3;
    const int grp = lane >> 2;
    const int m0 = blockIdx.x * 128;
    const int n0 = blockIdx.y * 64;

    const int am0 = tid >> 2;
    const int am1 = am0 + 64;
    const int akp = (tid & 3) * 2;
    const int bn = tid & 63;
    const int bkh = tid >> 6;

    float acc[2][4][4];
#pragma unroll
    for (int mf = 0; mf < 2; ++mf)
#pragma unroll
        for (int nf = 0; nf < 4; ++nf)
#pragma unroll
            for (int j = 0; j < 4; ++j) acc[mf][nf][j] = 0.f;

    float4 va0 = make_float4(0.f, 0.f, 0.f, 0.f);
    float4 va1 = make_float4(0.f, 0.f, 0.f, 0.f);
    float pb0, pb1, pb2, pb3;
    if (m0 + am0 < M) va0 = *(const float4*)&A[(size_t)(m0 + am0) * K + akp * 2];
    if (m0 + am1 < M) va1 = *(const float4*)&A[(size_t)(m0 + am1) * K + akp * 2];
    pb0 = B[(size_t)(2 * bkh) * ldb + n0 + bn];
    pb1 = B[(size_t)(2 * bkh + 1) * ldb + n0 + bn];
    pb2 = B[(size_t)(2 * (bkh + 4)) * ldb + n0 + bn];
    pb3 = B[(size_t)(2 * (bkh + 4) + 1) * ldb + n0 + bn];

    for (int k0 = 0; k0 < K; k0 += 16) {
        {
            unsigned h, l;
            split2(va0.x, va0.y, h, l); Ah[akp][am0] = h;     Al[akp][am0] = l;
            split2(va0.z, va0.w, h, l); Ah[akp + 1][am0] = h; Al[akp + 1][am0] = l;
            split2(va1.x, va1.y, h, l); Ah[akp][am1] = h;     Al[akp][am1] = l;
            split2(va1.z, va1.w, h, l); Ah[akp + 1][am1] = h; Al[akp + 1][am1] = l;
            split2(pb0, pb1, h, l); Bh[bkh][bn] = h;     Bl[bkh][bn] = l;
            split2(pb2, pb3, h, l); Bh[bkh + 4][bn] = h; Bl[bkh + 4][bn] = l;
        }
        __syncthreads();

        if (k0 + 16 < K) {
            va0 = make_float4(0.f, 0.f, 0.f, 0.f);
            va1 = make_float4(0.f, 0.f, 0.f, 0.f);
            if (m0 + am0 < M) va0 = *(const float4*)&A[(size_t)(m0 + am0) * K + k0 + 16 + akp * 2];
            if (m0 + am1 < M) va1 = *(const float4*)&A[(size_t)(m0 + am1) * K + k0 + 16 + akp * 2];
            pb0 = B[(size_t)(k0 + 16 + 2 * bkh) * ldb + n0 + bn];
            pb1 = B[(size_t)(k0 + 16 + 2 * bkh + 1) * ldb + n0 + bn];
            pb2 = B[(size_t)(k0 + 16 + 2 * (bkh + 4)) * ldb + n0 + bn];
            pb3 = B[(size_t)(k0 + 16 + 2 * (bkh + 4) + 1) * ldb + n0 + bn];
        }

        unsigned ah[2][4], al_[2][4];
#pragma unroll
        for (int mf = 0; mf < 2; ++mf) {
            int mb = warp_m * 32 + mf * 16 + grp;
            ah[mf][0] = Ah[tig][mb];      al_[mf][0] = Al[tig][mb];
            ah[mf][1] = Ah[tig][mb + 8];  al_[mf][1] = Al[tig][mb + 8];
            ah[mf][2] = Ah[tig + 4][mb];      al_[mf][2] = Al[tig + 4][mb];
            ah[mf][3] = Ah[tig + 4][mb + 8];  al_[mf][3] = Al[tig + 4][mb + 8];
        }
#pragma unroll
        for (int nf = 0; nf < 4; ++nf) {
            int n = warp_n * 32 + nf * 8 + grp;
            unsigned bh0 = Bh[tig][n], bh1 = Bh[tig + 4][n];
            unsigned bl0 = Bl[tig][n], bl1 = Bl[tig + 4][n];
#pragma unroll
            for (int mf = 0; mf < 2; ++mf) {
                mma16(acc[mf][nf], ah[mf][0], ah[mf][1], ah[mf][2], ah[mf][3], bh0, bh1);
                mma16(acc[mf][nf], al_[mf][0], al_[mf][1], al_[mf][2], al_[mf][3], bh0, bh1);
                mma16(acc[mf][nf], ah[mf][0], ah[mf][1], ah[mf][2], ah[mf][3], bl0, bl1);
            }
        }
        __syncthreads();
    }

#pragma unroll
    for (int mf = 0; mf < 2; ++mf) {
        int r0 = m0 + warp_m * 32 + mf * 16 + grp;
        int r1 = r0 + 8;
#pragma unroll
        for (int nf = 0; nf < 4; ++nf) {
            int c = n0 + warp_n * 32 + nf * 8 + tig * 2;
            if (r0 < M)
                *(float2*)&C[(size_t)r0 * ldc + c] = make_float2(acc[mf][nf][0], acc[mf][nf][1]);
            if (r1 < M)
                *(float2*)&C[(size_t)r1 * ldc + c] = make_float2(acc[mf][nf][2], acc[mf][nf][3]);
        }
    }
}

// ---------------- CSR build ----------------
__global__ __launch_bounds__(256) void zero_cnt_kernel()
{
    int i = blockIdx.x * blockDim.x + threadIdx.x;
    if (i < N_NODES) g_cnt[i] = 0;
}
__global__ __launch_bounds__(256) void count_kernel(const int* __restrict__ ei)
{
    int e = blockIdx.x * blockDim.x + threadIdx.x;
    if (e < N_EDGES) atomicAdd(&g_cnt[ei[N_EDGES + e]], 1);
}
__global__ __launch_bounds__(256) void scan1_kernel()
{
    __shared__ int sh[256];
    int i = blockIdx.x * 256 + threadIdx.x;
    int v = (i < N_NODES) ? g_cnt[i] : 0;
    sh[threadIdx.x] = v;
    __syncthreads();
#pragma unroll
    for (int off = 1; off < 256; off <<= 1) {
        int t = 0;
        if (threadIdx.x >= off) t = sh[threadIdx.x - off];
        __syncthreads();
        if (threadIdx.x >= off) sh[threadIdx.x] += t;
        __syncthreads();
    }
    if (i < N_NODES) g_off[i + 1] = sh[threadIdx.x];
    if (threadIdx.x == 255) g_bsum[blockIdx.x] = sh[255];
    if (i == 0) g_off[0] = 0;
}
__global__ __launch_bounds__(256) void scan2_kernel(int nblocks)
{
    __shared__ int sh[256];
    int t = threadIdx.x;
    int v = (t < nblocks) ? g_bsum[t] : 0;
    sh[t] = v;
    __syncthreads();
#pragma unroll
    for (int off = 1; off < 256; off <<= 1) {
        int u = 0;
        if (t >= off) u = sh[t - off];
        __syncthreads();
        if (t >= off) sh[t] += u;
        __syncthreads();
    }
    if (t < nblocks) g_bsum[t] = sh[t] - v;    // exclusive
}
__global__ __launch_bounds__(256) void scan3_kernel()
{
    int i = blockIdx.x * 256 + threadIdx.x;
    if (i < N_NODES) {
        int v = g_off[i + 1] + g_bsum[blockIdx.x];
        g_off[i + 1] = v;
        if (i + 1 < N_NODES) g_fill[i + 1] = v;
        if (i == 0) g_fill[0] = 0;
    }
}
__global__ __launch_bounds__(256) void scatter_kernel(const int* __restrict__ ei)
{
    int e = blockIdx.x * blockDim.x + threadIdx.x;
    if (e >= N_EDGES) return;
    int s = ei[e], d = ei[N_EDGES + e];
    int pos = atomicAdd(&g_fill[d], 1);
    g_csrc[pos] = s;
}

// -------- gather attention: TWO warps per node (even/odd CSR entries) ------
// Halves each warp's serial latency chain; smem combine + unchanged epilogue.
__global__ __launch_bounds__(256) void gat_gather_kernel(const float* __restrict__ b)
{
    __shared__ float sAcc0[4][128], sAcc1[4][128];   // odd-warp partials
    __shared__ float sDen[4][8];

    const int warp = threadIdx.x >> 5, lane = threadIdx.x & 31;
    const int pair = warp >> 1, half = warp & 1;
    const int n = blockIdx.x * 4 + pair;
    const unsigned FULL = 0xffffffffu;
    const int h0 = lane >> 3, h1 = 4 + (lane >> 3);

    float myasrc = 0.f, myadst = 0.f;
    if (n < N_NODES && lane < 8) {
        myasrc = g_asrc[n * 8 + lane];
        myadst = g_adst[n * 8 + lane];
    }
    float4 acc0 = make_float4(0.f, 0.f, 0.f, 0.f);
    float4 acc1 = make_float4(0.f, 0.f, 0.f, 0.f);
    float denom = 0.f;

    if (n < N_NODES) {
        const int beg = g_off[n], end = g_off[n + 1];
        for (int i = beg + half; i < end; i += 2) {
            int s = g_csrc[i];
            float w = 0.f;
            if (lane < 8) {
                w = expf(leaky(g_asrc[s * 8 + lane] + myadst));
                denom += w;
            }
            float al0 = __shfl_sync(FULL, w, h0);
            float al1 = __shfl_sync(FULL, w, h1);
            float4 v0 = *(const float4*)&g_h[(size_t)s * 256 + lane * 4];
            float4 v1 = *(const float4*)&g_h[(size_t)s * 256 + 128 + lane * 4];
            acc0.x += al0 * v0.x; acc0.y += al0 * v0.y;
            acc0.z += al0 * v0.z; acc0.w += al0 * v0.w;
            acc1.x += al1 * v1.x; acc1.y += al1 * v1.y;
            acc1.z += al1 * v1.z; acc1.w += al1 * v1.w;
        }
        if (half == 0) {            // self loop handled by even warp
            float w = 0.f;
            if (lane < 8) {
                w = expf(leaky(myasrc + myadst));
                denom += w;
            }
            float al0 = __shfl_sync(FULL, w, h0);
            float al1 = __shfl_sync(FULL, w, h1);
            float4 v0 = *(const float4*)&g_h[(size_t)n * 256 + lane * 4];
            float4 v1 = *(const float4*)&g_h[(size_t)n * 256 + 128 + lane * 4];
            acc0.x += al0 * v0.x; acc0.y += al0 * v0.y;
            acc0.z += al0 * v0.z; acc0.w += al0 * v0.w;
            acc1.x += al1 * v1.x; acc1.y += al1 * v1.y;
            acc1.z += al1 * v1.z; acc1.w += al1 * v1.w;
        }
    }
    // odd warp publishes partials
    if (half == 1) {
        *(float4*)&sAcc0[pair][lane * 4] = acc0;
        *(float4*)&sAcc1[pair][lane * 4] = acc1;
        if (lane < 8) sDen[pair][lane] = denom;
    }
    __syncthreads();
    if (half == 0 && n < N_NODES) {
        float4 o0 = *(float4*)&sAcc0[pair][lane * 4];
        float4 o1 = *(float4*)&sAcc1[pair][lane * 4];
        acc0.x += o0.x; acc0.y += o0.y; acc0.z += o0.z; acc0.w += o0.w;
        acc1.x += o1.x; acc1.y += o1.y; acc1.z += o1.z; acc1.w += o1.w;
        if (lane < 8) denom += sDen[pair][lane];

        float inv0 = 1.f / __shfl_sync(FULL, denom, h0);
        float inv1 = 1.f / __shfl_sync(FULL, denom, h1);
        float4 bb0 = *(const float4*)&b[lane * 4];
        float4 bb1 = *(const float4*)&b[128 + lane * 4];
        float4 q0, q1;
        q0.x = fmaxf(acc0.x * inv0 + bb0.x, 0.f);
        q0.y = fmaxf(acc0.y * inv0 + bb0.y, 0.f);
        q0.z = fmaxf(acc0.z * inv0 + bb0.z, 0.f);
        q0.w = fmaxf(acc0.w * inv0 + bb0.w, 0.f);
        q1.x = fmaxf(acc1.x * inv1 + bb1.x, 0.f);
        q1.y = fmaxf(acc1.y * inv1 + bb1.y, 0.f);
        q1.z = fmaxf(acc1.z * inv1 + bb1.z, 0.f);
        q1.w = fmaxf(acc1.w * inv1 + bb1.w, 0.f);
        *(float4*)&g_x[(size_t)n * 256 + lane * 4] = q0;
        *(float4*)&g_x[(size_t)n * 256 + 128 + lane * 4] = q1;
    }
}

// ---------------- pack Wcat = [Wp1_a | Wp1_b] : [256 x 64] ----------------
__global__ __launch_bounds__(256) void pack_wcat_kernel(const float* __restrict__ Wp1)
{
    int i = blockIdx.x * blockDim.x + threadIdx.x;
    if (i >= 256 * 64) return;
    int k = i >> 6, j = i & 63;
    g_wcat[i] = (j < 32) ? Wp1[k * 32 + j] : Wp1[(256 + k) * 32 + (j - 32)];
}

// ------- edge predictor: bf16-split tensor-core edge-MLP + exact combine ---
__global__ __launch_bounds__(128) void edge_pred_kernel(
    const int* __restrict__ ei, const float* __restrict__ edge_attr,
    const float* __restrict__ Wm1, const float* __restrict__ bm1,
    const float* __restrict__ Wm2, const float* __restrict__ bm2,
    const float* __restrict__ Wp1, const float* __restrict__ bp1,
    const float* __restrict__ Wp2, const float* __restrict__ bp2,
    float* __restrict__ out)
{
    __shared__ unsigned XH[16][66], XL[16][66];    // ping buffer
    __shared__ unsigned YH[16][66], YL[16][66];    // pong buffer
    __shared__ unsigned W1h[16][33], W1l[16][33];
    __shared__ unsigned W2h[16][33], W2l[16][33];
    __shared__ unsigned W3h[16][33], W3l[16][33];
    __shared__ int   sRow[64], sCol[64];
    __shared__ float sB[64];                       // bm1 | bm2

    const int tid = threadIdx.x;
    const int lane = tid & 31;
    const int wrp = tid >> 5;
    const int tig = lane & 3;
    const int grp = lane >> 2;
    const int e0 = blockIdx.x * 64;
    const int m0l = wrp * 16 + grp;                // local edge row (0..63)

    if (tid < 64) {
        sRow[tid] = ei[e0 + tid];
        sCol[tid] = ei[N_EDGES + e0 + tid];
    }
    if (tid < 32) { sB[tid] = bm1[tid]; sB[32 + tid] = bm2[tid]; }

    for (int i = tid; i < 512; i += 128) {
        int kp = i >> 5, n = i & 31;
        unsigned h, l;
        split2(Wm1[(2 * kp) * 32 + n], Wm1[(2 * kp + 1) * 32 + n], h, l);
        W1h[kp][n] = h; W1l[kp][n] = l;
        split2(Wm2[(2 * kp) * 32 + n], Wm2[(2 * kp + 1) * 32 + n], h, l);
        W2h[kp][n] = h; W2l[kp][n] = l;
        split2(Wp1[(512 + 2 * kp) * 32 + n], Wp1[(512 + 2 * kp + 1) * 32 + n], h, l);
        W3h[kp][n] = h; W3l[kp][n] = l;
    }
    for (int f = tid; f < 512; f += 128) {
        int e = f >> 3, q = f & 7;
        float4 v = *(const float4*)&edge_attr[(size_t)(e0 + e) * 32 + q * 4];
        unsigned h, l;
        split2(v.x, v.y, h, l); XH[2 * q][e] = h;     XL[2 * q][e] = l;
        split2(v.z, v.w, h, l); XH[2 * q + 1][e] = h; XL[2 * q + 1][e] = l;
    }
    __syncthreads();

    float acc[4][4];

#define EP_COMPUTE(IH, IL, WH, WL)                                            \
    {                                                                         \
        _Pragma("unroll")                                                     \
        for (int nf = 0; nf < 4; ++nf)                                        \
            _Pragma("unroll")                                                 \
            for (int j = 0; j < 4; ++j) acc[nf][j] = 0.f;                     \
        _Pragma("unroll")                                                     \
        for (int ks = 0; ks < 2; ++ks) {                                      \
            int kb = ks * 8;                                                  \
            unsigned a0 = IH[kb + tig][m0l],     l0 = IL[kb + tig][m0l];      \
            unsigned a1 = IH[kb + tig][m0l + 8], l1 = IL[kb + tig][m0l + 8];  \
            unsigned a2 = IH[kb + tig + 4][m0l],     l2 = IL[kb + tig + 4][m0l];     \
            unsigned a3 = IH[kb + tig + 4][m0l + 8], l3 = IL[kb + tig + 4][m0l + 8]; \
            _Pragma("unroll")                                                 \
            for (int nf = 0; nf < 4; ++nf) {                                  \
                int n = nf * 8 + grp;                                         \
                unsigned bh0 = WH[kb + tig][n], bh1 = WH[kb + tig + 4][n];    \
                unsigned bl0 = WL[kb + tig][n], bl1 = WL[kb + tig + 4][n];    \
                mma16(acc[nf], a0, a1, a2, a3, bh0, bh1);                     \
                mma16(acc[nf], l0, l1, l2, l3, bh0, bh1);                     \
                mma16(acc[nf], a0, a1, a2, a3, bl0, bl1);                     \
            }                                                                 \
        }                                                                     \
    }
#define EP_STORE(OH, OL, boff)                                                \
    {                                                                         \
        _Pragma("unroll")                                                     \
        for (int nf = 0; nf < 4; ++nf) {                                      \
            int j0 = nf * 8 + 2 * tig;                                        \
            int kp = nf * 4 + tig;                                            \
            float b0 = sB[boff + j0], b1 = sB[boff + j0 + 1];                 \
            float v0 = fmaxf(acc[nf][0] + b0, 0.f);                           \
            float v1 = fmaxf(acc[nf][1] + b1, 0.f);                           \
            float v2 = fmaxf(acc[nf][2] + b0, 0.f);                           \
            float v3 = fmaxf(acc[nf][3] + b1, 0.f);                           \
            unsigned h, l;                                                    \
            split2(v0, v1, h, l); OH[kp][m0l] = h;     OL[kp][m0l] = l;       \
            split2(v2, v3, h, l); OH[kp][m0l + 8] = h; OL[kp][m0l + 8] = l;   \
        }                                                                     \
    }

    EP_COMPUTE(XH, XL, W1h, W1l)
    EP_STORE(YH, YL, 0)
    __syncwarp();
    EP_COMPUTE(YH, YL, W2h, W2l)
    EP_STORE(XH, XL, 32)
    __syncwarp();
    EP_COMPUTE(XH, XL, W3h, W3l)

#undef EP_COMPUTE
#undef EP_STORE

    const int r0n = sRow[m0l],     c0n = sCol[m0l];
    const int r1n = sRow[m0l + 8], c1n = sCol[m0l + 8];
    float acc_r0 = 0.f, acc_r1 = 0.f;
#pragma unroll
    for (int nf = 0; nf < 4; ++nf) {
        int j0 = nf * 8 + 2 * tig;
        float2 pa0 = *(const float2*)&g_p[(size_t)r0n * 64 + j0];
        float2 pb0 = *(const float2*)&g_p[(size_t)c0n * 64 + 32 + j0];
        float2 pa1 = *(const float2*)&g_p[(size_t)r1n * 64 + j0];
        float2 pb1 = *(const float2*)&g_p[(size_t)c1n * 64 + 32 + j0];
        float b0 = bp1[j0], b1 = bp1[j0 + 1];
        float w0 = Wp2[j0], w1 = Wp2[j0 + 1];
        float h;
        h = acc[nf][0] + pa0.x + pb0.x + b0; acc_r0 += fmaxf(h, 0.f) * w0;
        h = acc[nf][1] + pa0.y + pb0.y + b1; acc_r0 += fmaxf(h, 0.f) * w1;
        h = acc[nf][2] + pa1.x + pb1.x + b0; acc_r1 += fmaxf(h, 0.f) * w0;
        h = acc[nf][3] + pa1.y + pb1.y + b1; acc_r1 += fmaxf(h, 0.f) * w1;
    }
    acc_r0 += __shfl_xor_sync(0xffffffffu, acc_r0, 1);
    acc_r0 += __shfl_xor_sync(0xffffffffu, acc_r0, 2);
    acc_r1 += __shfl_xor_sync(0xffffffffu, acc_r1, 1);
    acc_r1 += __shfl_xor_sync(0xffffffffu, acc_r1, 2);
    if (tig == 0) {
        float bias2 = bp2[0];
        out[e0 + m0l]     = acc_r0 + bias2;
        out[e0 + m0l + 8] = acc_r1 + bias2;
    }
}

// ---------------- host ----------------
extern "C" void kernel_launch(void* const* d_in, const int* in_sizes, int n_in,
                              void* d_out, int out_size)
{
    const float* x   = (const float*)d_in[0];
    const int*   ei  = (const int*)d_in[1];
    const float* ea  = (const float*)d_in[2];
    const float* W1  = (const float*)d_in[3];
    const float* as1 = (const float*)d_in[4];
    const float* ad1 = (const float*)d_in[5];
    const float* b1  = (const float*)d_in[6];
    const float* W2  = (const float*)d_in[7];
    const float* as2 = (const float*)d_in[8];
    const float* ad2 = (const float*)d_in[9];
    const float* b2  = (const float*)d_in[10];
    const float* Wm1 = (const float*)d_in[11];
    const float* bm1 = (const float*)d_in[12];
    const float* Wm2 = (const float*)d_in[13];
    const float* bm2 = (const float*)d_in[14];
    const float* Wp1 = (const float*)d_in[15];
    const float* bp1 = (const float*)d_in[16];
    const float* Wp2 = (const float*)d_in[17];
    const float* bp2 = (const float*)d_in[18];
    float* out = (float*)d_out;

    float *ph = nullptr, *px = nullptr, *pw = nullptr, *pp = nullptr;
    cudaGetSymbolAddress((void**)&ph, g_h);
    cudaGetSymbolAddress((void**)&px, g_x);
    cudaGetSymbolAddress((void**)&pw, g_wcat);
    cudaGetSymbolAddress((void**)&pp, g_p);

    const int EB  = (N_EDGES + 255) / 256;
    const int NB  = (N_NODES + 255) / 256;
    const int NWB = (N_NODES + 3) / 4;         // 2 warps/node, 4 nodes/block

    // ---- CSR build (once; reused by both layers) ----
    zero_cnt_kernel<<<NB, 256>>>();
    count_kernel<<<EB, 256>>>(ei);
    scan1_kernel<<<NB, 256>>>();
    scan2_kernel<<<1, 256>>>(NB);
    scan3_kernel<<<NB, 256>>>();
    scatter_kernel<<<EB, 256>>>(ei);

    for (int layer = 0; layer < 2; ++layer) {
        const float* X   = layer ? px : x;
        const int    K   = layer ? 256 : 128;
        const float* W   = layer ? W2 : W1;
        const float* as_ = layer ? as2 : as1;
        const float* ad_ = layer ? ad2 : ad1;
        const float* b_  = layer ? b2 : b1;

        tc_gemm128_kernel<<<dim3(391, 2), 256>>>(X, W, ph, N_NODES, K, 256, 256, as_, ad_);
        gat_gather_kernel<<<NWB, 256>>>(b_);
    }
    pack_wcat_kernel<<<64, 256>>>(Wp1);
    tc_gemm_kernel<<<dim3(391, 1), 256>>>(px, pw, pp, N_NODES, 256, 64, 64);
    edge_pred_kernel<<<N_EDGES / 64, 128>>>(ei, ea,
                                            Wm1, bm1, Wm2, bm2,
                                            Wp1, bp1, Wp2, bp2, out);
}

// round 17
// speedup vs baseline: 1.6088x; 1.6088x over previous
#include <cuda_runtime.h>
#include <cuda_bf16.h>
#include <math.h>

#define N_NODES 50000
#define N_EDGES 400000
#define HEADS 8
#define HID 32
#define F 256            // HEADS*HID
#define NEG 0.2f

// ---------------- scratch (device globals: allocation-free) ----------------
__device__ float g_h[N_NODES * F];        // X @ W (pre-attention features)
__device__ float g_x[N_NODES * F];        // layer output
__device__ float g_asrc[N_NODES * HEADS];
__device__ float g_adst[N_NODES * HEADS];
__device__ float g_p[N_NODES * 64];       // [P_a | P_b] node projections
__device__ float g_wcat[256 * 64];        // [Wp1_a | Wp1_b] packed
__device__ int   g_cnt[N_NODES];
__device__ int   g_off[N_NODES + 1];
__device__ int   g_fill[N_NODES];
__device__ int   g_bsum[256];
__device__ int   g_csrc[N_EDGES];

__device__ __forceinline__ float leaky(float x) { return x > 0.f ? x : NEG * x; }

// pack two floats to bf16x2 (x in low half = first k element)
__device__ __forceinline__ unsigned pk(float x, float y) {
    __nv_bfloat162 h = __floats2bfloat162_rn(x, y);
    return *(unsigned*)&h;
}
__device__ __forceinline__ void split2(float x, float y, unsigned& hi, unsigned& lo) {
    float hx = __bfloat162float(__float2bfloat16_rn(x));
    float hy = __bfloat162float(__float2bfloat16_rn(y));
    hi = pk(hx, hy);
    lo = pk(x - hx, y - hy);
}

__device__ __forceinline__ void mma16(float* c,
    unsigned a0, unsigned a1, unsigned a2, unsigned a3,
    unsigned b0, unsigned b1)
{
    asm volatile(
        "mma.sync.aligned.m16n8k16.row.col.f32.bf16.bf16.f32 "
        "{%0,%1,%2,%3}, {%4,%5,%6,%7}, {%8,%9}, {%0,%1,%2,%3};"
        : "+f"(c[0]), "+f"(c[1]), "+f"(c[2]), "+f"(c[3])
        : "r"(a0), "r"(a1), "r"(a2), "r"(a3), "r"(b0), "r"(b1));
}

// ------ layer GEMM: tile 128x128, BK=16, 3x bf16 split, attention epilogue -
// 256 threads = 8 warps (4 warp_m x 2 warp_n), warp tile 32x64 (2 heads).
// Smem double-buffered: ONE __syncthreads per k-tile.
__global__ __launch_bounds__(256) void tc_gemm128_kernel(
    const float* __restrict__ A, const float* __restrict__ B,
    float* __restrict__ C, int M, int K, int ldb, int ldc,
    const float* __restrict__ a_src, const float* __restrict__ a_dst)
{
    __shared__ unsigned Ah[2][8][132], Al[2][8][132];
    __shared__ unsigned Bh[2][8][132], Bl[2][8][132];
    __shared__ float sAs[128], sAd[128];

    const int tid = threadIdx.x;
    const int lane = tid & 31;
    const int wid = tid >> 5;
    const int warp_m = wid >> 1;          // rows warp_m*32
    const int warp_n = wid & 1;           // cols warp_n*64
    const int tig = lane & 3;
    const int grp = lane >> 2;
    const int m0 = blockIdx.x * 128;
    const int n0 = blockIdx.y * 128;

    if (tid < 128) {
        sAs[tid] = a_src[n0 + tid];
        sAd[tid] = a_dst[n0 + tid];
    }

    const int am0 = tid >> 2;             // 0..63
    const int am1 = am0 + 64;             // 64..127
    const int akp = (tid & 3) * 2;
    const int bn = tid & 127;
    const int bkh = tid >> 7;             // 0 or 1

    float acc[2][8][4];
#pragma unroll
    for (int mf = 0; mf < 2; ++mf)
#pragma unroll
        for (int nf = 0; nf < 8; ++nf)
#pragma unroll
            for (int j = 0; j < 4; ++j) acc[mf][nf][j] = 0.f;

    // ---- prologue: prefetch tile 0 ----
    float4 va0 = make_float4(0.f, 0.f, 0.f, 0.f);
    float4 va1 = make_float4(0.f, 0.f, 0.f, 0.f);
    float pb[8];
    if (m0 + am0 < M) va0 = *(const float4*)&A[(size_t)(m0 + am0) * K + akp * 2];
    if (m0 + am1 < M) va1 = *(const float4*)&A[(size_t)(m0 + am1) * K + akp * 2];
#pragma unroll
    for (int q = 0; q < 4; ++q) {
        int kp = bkh + 2 * q;
        pb[2 * q]     = B[(size_t)(2 * kp) * ldb + n0 + bn];
        pb[2 * q + 1] = B[(size_t)(2 * kp + 1) * ldb + n0 + bn];
    }

    int buf = 0;
    for (int k0 = 0; k0 < K; k0 += 16) {
        {
            unsigned h, l;
            split2(va0.x, va0.y, h, l); Ah[buf][akp][am0] = h;     Al[buf][akp][am0] = l;
            split2(va0.z, va0.w, h, l); Ah[buf][akp + 1][am0] = h; Al[buf][akp + 1][am0] = l;
            split2(va1.x, va1.y, h, l); Ah[buf][akp][am1] = h;     Al[buf][akp][am1] = l;
            split2(va1.z, va1.w, h, l); Ah[buf][akp + 1][am1] = h; Al[buf][akp + 1][am1] = l;
#pragma unroll
            for (int q = 0; q < 4; ++q) {
                int kp = bkh + 2 * q;
                split2(pb[2 * q], pb[2 * q + 1], h, l);
                Bh[buf][kp][bn] = h; Bl[buf][kp][bn] = l;
            }
        }
        __syncthreads();

        if (k0 + 16 < K) {
            va0 = make_float4(0.f, 0.f, 0.f, 0.f);
            va1 = make_float4(0.f, 0.f, 0.f, 0.f);
            if (m0 + am0 < M) va0 = *(const float4*)&A[(size_t)(m0 + am0) * K + k0 + 16 + akp * 2];
            if (m0 + am1 < M) va1 = *(const float4*)&A[(size_t)(m0 + am1) * K + k0 + 16 + akp * 2];
#pragma unroll
            for (int q = 0; q < 4; ++q) {
                int kp = bkh + 2 * q;
                pb[2 * q]     = B[(size_t)(k0 + 16 + 2 * kp) * ldb + n0 + bn];
                pb[2 * q + 1] = B[(size_t)(k0 + 16 + 2 * kp + 1) * ldb + n0 + bn];
            }
        }

        unsigned ah[2][4], al_[2][4];
#pragma unroll
        for (int mf = 0; mf < 2; ++mf) {
            int mb = warp_m * 32 + mf * 16 + grp;
            ah[mf][0] = Ah[buf][tig][mb];      al_[mf][0] = Al[buf][tig][mb];
            ah[mf][1] = Ah[buf][tig][mb + 8];  al_[mf][1] = Al[buf][tig][mb + 8];
            ah[mf][2] = Ah[buf][tig + 4][mb];      al_[mf][2] = Al[buf][tig + 4][mb];
            ah[mf][3] = Ah[buf][tig + 4][mb + 8];  al_[mf][3] = Al[buf][tig + 4][mb + 8];
        }
#pragma unroll
        for (int nf = 0; nf < 8; ++nf) {
            int n = warp_n * 64 + nf * 8 + grp;
            unsigned bh0 = Bh[buf][tig][n], bh1 = Bh[buf][tig + 4][n];
            unsigned bl0 = Bl[buf][tig][n], bl1 = Bl[buf][tig + 4][n];
#pragma unroll
            for (int mf = 0; mf < 2; ++mf) {
                mma16(acc[mf][nf], ah[mf][0], ah[mf][1], ah[mf][2], ah[mf][3], bh0, bh1);
                mma16(acc[mf][nf], al_[mf][0], al_[mf][1], al_[mf][2], al_[mf][3], bh0, bh1);
                mma16(acc[mf][nf], ah[mf][0], ah[mf][1], ah[mf][2], ah[mf][3], bl0, bl1);
            }
        }
        buf ^= 1;        // next store targets the other buffer — no trailing sync
    }

    // ---- store C ----
#pragma unroll
    for (int mf = 0; mf < 2; ++mf) {
        int r0 = m0 + warp_m * 32 + mf * 16 + grp;
        int r1 = r0 + 8;
#pragma unroll
        for (int nf = 0; nf < 8; ++nf) {
            int c = n0 + warp_n * 64 + nf * 8 + tig * 2;
            if (r0 < M)
                *(float2*)&C[(size_t)r0 * ldc + c] = make_float2(acc[mf][nf][0], acc[mf][nf][1]);
            if (r1 < M)
                *(float2*)&C[(size_t)r1 * ldc + c] = make_float2(acc[mf][nf][2], acc[mf][nf][3]);
        }
    }

    // ---- attention dots: warp spans 2 heads (nf 0..3 and nf 4..7) ----
#pragma unroll
    for (int mf = 0; mf < 2; ++mf) {
#pragma unroll
        for (int half = 0; half < 2; ++half) {
            const int head = (n0 >> 5) + warp_n * 2 + half;
            float ps0 = 0.f, pd0 = 0.f, ps1 = 0.f, pd1 = 0.f;
#pragma unroll
            for (int q = 0; q < 4; ++q) {
                int nf = half * 4 + q;
                int cl = warp_n * 64 + nf * 8 + tig * 2;
                float w0s = sAs[cl], w1s = sAs[cl + 1];
                float w0d = sAd[cl], w1d = sAd[cl + 1];
                ps0 += acc[mf][nf][0] * w0s + acc[mf][nf][1] * w1s;
                pd0 += acc[mf][nf][0] * w0d + acc[mf][nf][1] * w1d;
                ps1 += acc[mf][nf][2] * w0s + acc[mf][nf][3] * w1s;
                pd1 += acc[mf][nf][2] * w0d + acc[mf][nf][3] * w1d;
            }
#pragma unroll
            for (int off = 1; off <= 2; off <<= 1) {
                ps0 += __shfl_xor_sync(0xffffffffu, ps0, off);
                pd0 += __shfl_xor_sync(0xffffffffu, pd0, off);
                ps1 += __shfl_xor_sync(0xffffffffu, ps1, off);
                pd1 += __shfl_xor_sync(0xffffffffu, pd1, off);
            }
            if (tig == 0) {
                int r0 = m0 + warp_m * 32 + mf * 16 + grp;
                int r1 = r0 + 8;
                if (r0 < M) { g_asrc[r0 * 8 + head] = ps0; g_adst[r0 * 8 + head] = pd0; }
                if (r1 < M) { g_asrc[r1 * 8 + head] = ps1; g_adst[r1 * 8 + head] = pd1; }
            }
        }
    }
}

// ------ proj GEMM: tile 128x64, BK=16 (round-12 verified kernel) -----------
__global__ __launch_bounds__(256) void tc_gemm_kernel(
    const float* __restrict__ A, const float* __restrict__ B,
    float* __restrict__ C, int M, int K, int ldb, int ldc)
{
    __shared__ unsigned Ah[8][132], Al[8][132];
    __shared__ unsigned Bh[8][68],  Bl[8][68];

    const int tid = threadIdx.x;
    const int lane = tid & 31;
    const int wid = tid >> 5;
    const int warp_m = wid >> 1;
    const int warp_n = wid & 1;
    const int tig = lane & 3;
    const int grp = lane >> 2;
    const int m0 = blockIdx.x * 128;
    const int n0 = blockIdx.y * 64;

    const int am0 = tid >> 2;
    const int am1 = am0 + 64;
    const int akp = (tid & 3) * 2;
    const int bn = tid & 63;
    const int bkh = tid >> 6;

    float acc[2][4][4];
#pragma unroll
    for (int mf = 0; mf < 2; ++mf)
#pragma unroll
        for (int nf = 0; nf < 4; ++nf)
#pragma unroll
            for (int j = 0; j < 4; ++j) acc[mf][nf][j] = 0.f;

    float4 va0 = make_float4(0.f, 0.f, 0.f, 0.f);
    float4 va1 = make_float4(0.f, 0.f, 0.f, 0.f);
    float pb0, pb1, pb2, pb3;
    if (m0 + am0 < M) va0 = *(const float4*)&A[(size_t)(m0 + am0) * K + akp * 2];
    if (m0 + am1 < M) va1 = *(const float4*)&A[(size_t)(m0 + am1) * K + akp * 2];
    pb0 = B[(size_t)(2 * bkh) * ldb + n0 + bn];
    pb1 = B[(size_t)(2 * bkh + 1) * ldb + n0 + bn];
    pb2 = B[(size_t)(2 * (bkh + 4)) * ldb + n0 + bn];
    pb3 = B[(size_t)(2 * (bkh + 4) + 1) * ldb + n0 + bn];

    for (int k0 = 0; k0 < K; k0 += 16) {
        {
            unsigned h, l;
            split2(va0.x, va0.y, h, l); Ah[akp][am0] = h;     Al[akp][am0] = l;
            split2(va0.z, va0.w, h, l); Ah[akp + 1][am0] = h; Al[akp + 1][am0] = l;
            split2(va1.x, va1.y, h, l); Ah[akp][am1] = h;     Al[akp][am1] = l;
            split2(va1.z, va1.w, h, l); Ah[akp + 1][am1] = h; Al[akp + 1][am1] = l;
            split2(pb0, pb1, h, l); Bh[bkh][bn] = h;     Bl[bkh][bn] = l;
            split2(pb2, pb3, h, l); Bh[bkh + 4][bn] = h; Bl[bkh + 4][bn] = l;
        }
        __syncthreads();

        if (k0 + 16 < K) {
            va0 = make_float4(0.f, 0.f, 0.f, 0.f);
            va1 = make_float4(0.f, 0.f, 0.f, 0.f);
            if (m0 + am0 < M) va0 = *(const float4*)&A[(size_t)(m0 + am0) * K + k0 + 16 + akp * 2];
            if (m0 + am1 < M) va1 = *(const float4*)&A[(size_t)(m0 + am1) * K + k0 + 16 + akp * 2];
            pb0 = B[(size_t)(k0 + 16 + 2 * bkh) * ldb + n0 + bn];
            pb1 = B[(size_t)(k0 + 16 + 2 * bkh + 1) * ldb + n0 + bn];
            pb2 = B[(size_t)(k0 + 16 + 2 * (bkh + 4)) * ldb + n0 + bn];
            pb3 = B[(size_t)(k0 + 16 + 2 * (bkh + 4) + 1) * ldb + n0 + bn];
        }

        unsigned ah[2][4], al_[2][4];
#pragma unroll
        for (int mf = 0; mf < 2; ++mf) {
            int mb = warp_m * 32 + mf * 16 + grp;
            ah[mf][0] = Ah[tig][mb];      al_[mf][0] = Al[tig][mb];
            ah[mf][1] = Ah[tig][mb + 8];  al_[mf][1] = Al[tig][mb + 8];
            ah[mf][2] = Ah[tig + 4][mb];      al_[mf][2] = Al[tig + 4][mb];
            ah[mf][3] = Ah[tig + 4][mb + 8];  al_[mf][3] = Al[tig + 4][mb + 8];
        }
#pragma unroll
        for (int nf = 0; nf < 4; ++nf) {
            int n = warp_n * 32 + nf * 8 + grp;
            unsigned bh0 = Bh[tig][n], bh1 = Bh[tig + 4][n];
            unsigned bl0 = Bl[tig][n], bl1 = Bl[tig + 4][n];
#pragma unroll
            for (int mf = 0; mf < 2; ++mf) {
                mma16(acc[mf][nf], ah[mf][0], ah[mf][1], ah[mf][2], ah[mf][3], bh0, bh1);
                mma16(acc[mf][nf], al_[mf][0], al_[mf][1], al_[mf][2], al_[mf][3], bh0, bh1);
                mma16(acc[mf][nf], ah[mf][0], ah[mf][1], ah[mf][2], ah[mf][3], bl0, bl1);
            }
        }
        __syncthreads();
    }

#pragma unroll
    for (int mf = 0; mf < 2; ++mf) {
        int r0 = m0 + warp_m * 32 + mf * 16 + grp;
        int r1 = r0 + 8;
#pragma unroll
        for (int nf = 0; nf < 4; ++nf) {
            int c = n0 + warp_n * 32 + nf * 8 + tig * 2;
            if (r0 < M)
                *(float2*)&C[(size_t)r0 * ldc + c] = make_float2(acc[mf][nf][0], acc[mf][nf][1]);
            if (r1 < M)
                *(float2*)&C[(size_t)r1 * ldc + c] = make_float2(acc[mf][nf][2], acc[mf][nf][3]);
        }
    }
}

// ---------------- CSR build ----------------
__global__ __launch_bounds__(256) void zero_cnt_kernel()
{
    int i = blockIdx.x * blockDim.x + threadIdx.x;
    if (i < N_NODES) g_cnt[i] = 0;
}
__global__ __launch_bounds__(256) void count_kernel(const int* __restrict__ ei)
{
    int e = blockIdx.x * blockDim.x + threadIdx.x;
    if (e < N_EDGES) atomicAdd(&g_cnt[ei[N_EDGES + e]], 1);
}
__global__ __launch_bounds__(256) void scan1_kernel()
{
    __shared__ int sh[256];
    int i = blockIdx.x * 256 + threadIdx.x;
    int v = (i < N_NODES) ? g_cnt[i] : 0;
    sh[threadIdx.x] = v;
    __syncthreads();
#pragma unroll
    for (int off = 1; off < 256; off <<= 1) {
        int t = 0;
        if (threadIdx.x >= off) t = sh[threadIdx.x - off];
        __syncthreads();
        if (threadIdx.x >= off) sh[threadIdx.x] += t;
        __syncthreads();
    }
    if (i < N_NODES) g_off[i + 1] = sh[threadIdx.x];
    if (threadIdx.x == 255) g_bsum[blockIdx.x] = sh[255];
    if (i == 0) g_off[0] = 0;
}
__global__ __launch_bounds__(256) void scan2_kernel(int nblocks)
{
    __shared__ int sh[256];
    int t = threadIdx.x;
    int v = (t < nblocks) ? g_bsum[t] : 0;
    sh[t] = v;
    __syncthreads();
#pragma unroll
    for (int off = 1; off < 256; off <<= 1) {
        int u = 0;
        if (t >= off) u = sh[t - off];
        __syncthreads();
        if (t >= off) sh[t] += u;
        __syncthreads();
    }
    if (t < nblocks) g_bsum[t] = sh[t] - v;    // exclusive
}
__global__ __launch_bounds__(256) void scan3_kernel()
{
    int i = blockIdx.x * 256 + threadIdx.x;
    if (i < N_NODES) {
        int v = g_off[i + 1] + g_bsum[blockIdx.x];
        g_off[i + 1] = v;
        if (i + 1 < N_NODES) g_fill[i + 1] = v;
        if (i == 0) g_fill[0] = 0;
    }
}
__global__ __launch_bounds__(256) void scatter_kernel(const int* __restrict__ ei)
{
    int e = blockIdx.x * blockDim.x + threadIdx.x;
    if (e >= N_EDGES) return;
    int s = ei[e], d = ei[N_EDGES + e];
    int pos = atomicAdd(&g_fill[d], 1);
    g_csrc[pos] = s;
}

// -------- gather attention: one warp per node, fused softmax+agg+relu ------
// (round-4 body: proven local optimum — do not restructure)
__global__ __launch_bounds__(256) void gat_gather_kernel(const float* __restrict__ b)
{
    const int warp = threadIdx.x >> 5, lane = threadIdx.x & 31;
    const int n = blockIdx.x * 8 + warp;
    if (n >= N_NODES) return;
    const unsigned FULL = 0xffffffffu;
    const int h0 = lane >> 3, h1 = 4 + (lane >> 3);

    float myasrc = 0.f, myadst = 0.f;
    if (lane < 8) {
        myasrc = g_asrc[n * 8 + lane];
        myadst = g_adst[n * 8 + lane];
    }
    float4 acc0 = make_float4(0.f, 0.f, 0.f, 0.f);
    float4 acc1 = make_float4(0.f, 0.f, 0.f, 0.f);
    float denom = 0.f;

    const int beg = g_off[n], end = g_off[n + 1];
    for (int i = beg; i < end; ++i) {
        int s = g_csrc[i];
        float w = 0.f;
        if (lane < 8) {
            w = expf(leaky(g_asrc[s * 8 + lane] + myadst));
            denom += w;
        }
        float al0 = __shfl_sync(FULL, w, h0);
        float al1 = __shfl_sync(FULL, w, h1);
        float4 v0 = *(const float4*)&g_h[(size_t)s * 256 + lane * 4];
        float4 v1 = *(const float4*)&g_h[(size_t)s * 256 + 128 + lane * 4];
        acc0.x += al0 * v0.x; acc0.y += al0 * v0.y;
        acc0.z += al0 * v0.z; acc0.w += al0 * v0.w;
        acc1.x += al1 * v1.x; acc1.y += al1 * v1.y;
        acc1.z += al1 * v1.z; acc1.w += al1 * v1.w;
    }
    // self loop
    {
        float w = 0.f;
        if (lane < 8) {
            w = expf(leaky(myasrc + myadst));
            denom += w;
        }
        float al0 = __shfl_sync(FULL, w, h0);
        float al1 = __shfl_sync(FULL, w, h1);
        float4 v0 = *(const float4*)&g_h[(size_t)n * 256 + lane * 4];
        float4 v1 = *(const float4*)&g_h[(size_t)n * 256 + 128 + lane * 4];
        acc0.x += al0 * v0.x; acc0.y += al0 * v0.y;
        acc0.z += al0 * v0.z; acc0.w += al0 * v0.w;
        acc1.x += al1 * v1.x; acc1.y += al1 * v1.y;
        acc1.z += al1 * v1.z; acc1.w += al1 * v1.w;
    }
    float inv0 = 1.f / __shfl_sync(FULL, denom, h0);
    float inv1 = 1.f / __shfl_sync(FULL, denom, h1);
    float4 bb0 = *(const float4*)&b[lane * 4];
    float4 bb1 = *(const float4*)&b[128 + lane * 4];
    float4 o0, o1;
    o0.x = fmaxf(acc0.x * inv0 + bb0.x, 0.f);
    o0.y = fmaxf(acc0.y * inv0 + bb0.y, 0.f);
    o0.z = fmaxf(acc0.z * inv0 + bb0.z, 0.f);
    o0.w = fmaxf(acc0.w * inv0 + bb0.w, 0.f);
    o1.x = fmaxf(acc1.x * inv1 + bb1.x, 0.f);
    o1.y = fmaxf(acc1.y * inv1 + bb1.y, 0.f);
    o1.z = fmaxf(acc1.z * inv1 + bb1.z, 0.f);
    o1.w = fmaxf(acc1.w * inv1 + bb1.w, 0.f);
    *(float4*)&g_x[(size_t)n * 256 + lane * 4] = o0;
    *(float4*)&g_x[(size_t)n * 256 + 128 + lane * 4] = o1;
}

// ---------------- pack Wcat = [Wp1_a | Wp1_b] : [256 x 64] ----------------
__global__ __launch_bounds__(256) void pack_wcat_kernel(const float* __restrict__ Wp1)
{
    int i = blockIdx.x * blockDim.x + threadIdx.x;
    if (i >= 256 * 64) return;
    int k = i >> 6, j = i & 63;
    g_wcat[i] = (j < 32) ? Wp1[k * 32 + j] : Wp1[(256 + k) * 32 + (j - 32)];
}

// ------- edge predictor: bf16-split tensor-core edge-MLP + exact combine ---
__global__ __launch_bounds__(128) void edge_pred_kernel(
    const int* __restrict__ ei, const float* __restrict__ edge_attr,
    const float* __restrict__ Wm1, const float* __restrict__ bm1,
    const float* __restrict__ Wm2, const float* __restrict__ bm2,
    const float* __restrict__ Wp1, const float* __restrict__ bp1,
    const float* __restrict__ Wp2, const float* __restrict__ bp2,
    float* __restrict__ out)
{
    __shared__ unsigned XH[16][66], XL[16][66];    // ping buffer
    __shared__ unsigned YH[16][66], YL[16][66];    // pong buffer
    __shared__ unsigned W1h[16][33], W1l[16][33];
    __shared__ unsigned W2h[16][33], W2l[16][33];
    __shared__ unsigned W3h[16][33], W3l[16][33];
    __shared__ int   sRow[64], sCol[64];
    __shared__ float sB[64];                       // bm1 | bm2

    const int tid = threadIdx.x;
    const int lane = tid & 31;
    const int wrp = tid >> 5;
    const int tig = lane & 3;
    const int grp = lane >> 2;
    const int e0 = blockIdx.x * 64;
    const int m0l = wrp * 16 + grp;                // local edge row (0..63)

    if (tid < 64) {
        sRow[tid] = ei[e0 + tid];
        sCol[tid] = ei[N_EDGES + e0 + tid];
    }
    if (tid < 32) { sB[tid] = bm1[tid]; sB[32 + tid] = bm2[tid]; }

    for (int i = tid; i < 512; i += 128) {
        int kp = i >> 5, n = i & 31;
        unsigned h, l;
        split2(Wm1[(2 * kp) * 32 + n], Wm1[(2 * kp + 1) * 32 + n], h, l);
        W1h[kp][n] = h; W1l[kp][n] = l;
        split2(Wm2[(2 * kp) * 32 + n], Wm2[(2 * kp + 1) * 32 + n], h, l);
        W2h[kp][n] = h; W2l[kp][n] = l;
        split2(Wp1[(512 + 2 * kp) * 32 + n], Wp1[(512 + 2 * kp + 1) * 32 + n], h, l);
        W3h[kp][n] = h; W3l[kp][n] = l;
    }
    for (int f = tid; f < 512; f += 128) {
        int e = f >> 3, q = f & 7;
        float4 v = *(const float4*)&edge_attr[(size_t)(e0 + e) * 32 + q * 4];
        unsigned h, l;
        split2(v.x, v.y, h, l); XH[2 * q][e] = h;     XL[2 * q][e] = l;
        split2(v.z, v.w, h, l); XH[2 * q + 1][e] = h; XL[2 * q + 1][e] = l;
    }
    __syncthreads();

    float acc[4][4];

#define EP_COMPUTE(IH, IL, WH, WL)                                            \
    {                                                                         \
        _Pragma("unroll")                                                     \
        for (int nf = 0; nf < 4; ++nf)                                        \
            _Pragma("unroll")                                                 \
            for (int j = 0; j < 4; ++j) acc[nf][j] = 0.f;                     \
        _Pragma("unroll")                                                     \
        for (int ks = 0; ks < 2; ++ks) {                                      \
            int kb = ks * 8;                                                  \
            unsigned a0 = IH[kb + tig][m0l],     l0 = IL[kb + tig][m0l];      \
            unsigned a1 = IH[kb + tig][m0l + 8], l1 = IL[kb + tig][m0l + 8];  \
            unsigned a2 = IH[kb + tig + 4][m0l],     l2 = IL[kb + tig + 4][m0l];     \
            unsigned a3 = IH[kb + tig + 4][m0l + 8], l3 = IL[kb + tig + 4][m0l + 8]; \
            _Pragma("unroll")                                                 \
            for (int nf = 0; nf < 4; ++nf) {                                  \
                int n = nf * 8 + grp;                                         \
                unsigned bh0 = WH[kb + tig][n], bh1 = WH[kb + tig + 4][n];    \
                unsigned bl0 = WL[kb + tig][n], bl1 = WL[kb + tig + 4][n];    \
                mma16(acc[nf], a0, a1, a2, a3, bh0, bh1);                     \
                mma16(acc[nf], l0, l1, l2, l3, bh0, bh1);                     \
                mma16(acc[nf], a0, a1, a2, a3, bl0, bl1);                     \
            }                                                                 \
        }                                                                     \
    }
#define EP_STORE(OH, OL, boff)                                                \
    {                                                                         \
        _Pragma("unroll")                                                     \
        for (int nf = 0; nf < 4; ++nf) {                                      \
            int j0 = nf * 8 + 2 * tig;                                        \
            int kp = nf * 4 + tig;                                            \
            float b0 = sB[boff + j0], b1 = sB[boff + j0 + 1];                 \
            float v0 = fmaxf(acc[nf][0] + b0, 0.f);                           \
            float v1 = fmaxf(acc[nf][1] + b1, 0.f);                           \
            float v2 = fmaxf(acc[nf][2] + b0, 0.f);                           \
            float v3 = fmaxf(acc[nf][3] + b1, 0.f);                           \
            unsigned h, l;                                                    \
            split2(v0, v1, h, l); OH[kp][m0l] = h;     OL[kp][m0l] = l;       \
            split2(v2, v3, h, l); OH[kp][m0l + 8] = h; OL[kp][m0l + 8] = l;   \
        }                                                                     \
    }

    EP_COMPUTE(XH, XL, W1h, W1l)
    EP_STORE(YH, YL, 0)
    __syncwarp();
    EP_COMPUTE(YH, YL, W2h, W2l)
    EP_STORE(XH, XL, 32)
    __syncwarp();
    EP_COMPUTE(XH, XL, W3h, W3l)

#undef EP_COMPUTE
#undef EP_STORE

    const int r0n = sRow[m0l],     c0n = sCol[m0l];
    const int r1n = sRow[m0l + 8], c1n = sCol[m0l + 8];
    float acc_r0 = 0.f, acc_r1 = 0.f;
#pragma unroll
    for (int nf = 0; nf < 4; ++nf) {
        int j0 = nf * 8 + 2 * tig;
        float2 pa0 = *(const float2*)&g_p[(size_t)r0n * 64 + j0];
        float2 pb0 = *(const float2*)&g_p[(size_t)c0n * 64 + 32 + j0];
        float2 pa1 = *(const float2*)&g_p[(size_t)r1n * 64 + j0];
        float2 pb1 = *(const float2*)&g_p[(size_t)c1n * 64 + 32 + j0];
        float b0 = bp1[j0], b1 = bp1[j0 + 1];
        float w0 = Wp2[j0], w1 = Wp2[j0 + 1];
        float h;
        h = acc[nf][0] + pa0.x + pb0.x + b0; acc_r0 += fmaxf(h, 0.f) * w0;
        h = acc[nf][1] + pa0.y + pb0.y + b1; acc_r0 += fmaxf(h, 0.f) * w1;
        h = acc[nf][2] + pa1.x + pb1.x + b0; acc_r1 += fmaxf(h, 0.f) * w0;
        h = acc[nf][3] + pa1.y + pb1.y + b1; acc_r1 += fmaxf(h, 0.f) * w1;
    }
    acc_r0 += __shfl_xor_sync(0xffffffffu, acc_r0, 1);
    acc_r0 += __shfl_xor_sync(0xffffffffu, acc_r0, 2);
    acc_r1 += __shfl_xor_sync(0xffffffffu, acc_r1, 1);
    acc_r1 += __shfl_xor_sync(0xffffffffu, acc_r1, 2);
    if (tig == 0) {
        float bias2 = bp2[0];
        out[e0 + m0l]     = acc_r0 + bias2;
        out[e0 + m0l + 8] = acc_r1 + bias2;
    }
}

// ---------------- host ----------------
extern "C" void kernel_launch(void* const* d_in, const int* in_sizes, int n_in,
                              void* d_out, int out_size)
{
    const float* x   = (const float*)d_in[0];
    const int*   ei  = (const int*)d_in[1];
    const float* ea  = (const float*)d_in[2];
    const float* W1  = (const float*)d_in[3];
    const float* as1 = (const float*)d_in[4];
    const float* ad1 = (const float*)d_in[5];
    const float* b1  = (const float*)d_in[6];
    const float* W2  = (const float*)d_in[7];
    const float* as2 = (const float*)d_in[8];
    const float* ad2 = (const float*)d_in[9];
    const float* b2  = (const float*)d_in[10];
    const float* Wm1 = (const float*)d_in[11];
    const float* bm1 = (const float*)d_in[12];
    const float* Wm2 = (const float*)d_in[13];
    const float* bm2 = (const float*)d_in[14];
    const float* Wp1 = (const float*)d_in[15];
    const float* bp1 = (const float*)d_in[16];
    const float* Wp2 = (const float*)d_in[17];
    const float* bp2 = (const float*)d_in[18];
    float* out = (float*)d_out;

    float *ph = nullptr, *px = nullptr, *pw = nullptr, *pp = nullptr;
    cudaGetSymbolAddress((void**)&ph, g_h);
    cudaGetSymbolAddress((void**)&px, g_x);
    cudaGetSymbolAddress((void**)&pw, g_wcat);
    cudaGetSymbolAddress((void**)&pp, g_p);

    const int EB  = (N_EDGES + 255) / 256;
    const int NB  = (N_NODES + 255) / 256;
    const int NWB = (N_NODES + 7) / 8;

    // ---- CSR build (once; reused by both layers) ----
    zero_cnt_kernel<<<NB, 256>>>();
    count_kernel<<<EB, 256>>>(ei);
    scan1_kernel<<<NB, 256>>>();
    scan2_kernel<<<1, 256>>>(NB);
    scan3_kernel<<<NB, 256>>>();
    scatter_kernel<<<EB, 256>>>(ei);

    for (int layer = 0; layer < 2; ++layer) {
        const float* X   = layer ? px : x;
        const int    K   = layer ? 256 : 128;
        const float* W   = layer ? W2 : W1;
        const float* as_ = layer ? as2 : as1;
        const float* ad_ = layer ? ad2 : ad1;
        const float* b_  = layer ? b2 : b1;

        tc_gemm128_kernel<<<dim3(391, 2), 256>>>(X, W, ph, N_NODES, K, 256, 256, as_, ad_);
        gat_gather_kernel<<<NWB, 256>>>(b_);
    }
    pack_wcat_kernel<<<64, 256>>>(Wp1);
    tc_gemm_kernel<<<dim3(391, 1), 256>>>(px, pw, pp, N_NODES, 256, 64, 64);
    edge_pred_kernel<<<N_EDGES / 64, 128>>>(ei, ea,
                                            Wm1, bm1, Wm2, bm2,
                                            Wp1, bp1, Wp2, bp2, out);
}